// round 7
// baseline (speedup 1.0000x reference)
#include <cuda_runtime.h>
#include <cuda_bf16.h>
#include <math.h>
#include <stdint.h>

#define TOKENS 4096
#define DDIM   1024

// ---------------------------------------------------------------------------
// scratch (__device__ globals; no cudaMalloc allowed)
// x/W1 hi+lo bf16, PRE-TILED into 16KB tiles (128 rows x 64 cols, SW128-swizzled)
// x: 32 mb x 16 kt = 512 tiles;  W1: 8 nb x 16 kt = 128 tiles
// ---------------------------------------------------------------------------
__device__ float g_s[TOKENS];
__device__ __align__(1024) uint4 g_xhi[512 * 1024];
__device__ __align__(1024) uint4 g_xlo[512 * 1024];
__device__ __align__(1024) uint4 g_whi[128 * 1024];
__device__ __align__(1024) uint4 g_wlo[128 * 1024];

__device__ __forceinline__ float softplusf(float z) {
    if (z > 20.0f) return z;
    return log1pf(expf(z));
}

__device__ __forceinline__ uint32_t smem_u32(const void* p) {
    uint32_t a;
    asm("{ .reg .u64 t; cvta.to.shared.u64 t, %1; cvt.u32.u64 %0, t; }"
        : "=r"(a) : "l"(p));
    return a;
}

#define MBARRIER_INIT(addr, cnt) \
    asm volatile("mbarrier.init.shared.b64 [%0], %1;" :: "r"(addr), "r"(cnt) : "memory")
#define MBARRIER_EXPECT_TX(addr, bytes) \
    asm volatile("mbarrier.arrive.expect_tx.shared.b64 _, [%0], %1;" \
        :: "r"(addr), "r"(bytes) : "memory")
#define MBARRIER_ARRIVE(addr) \
    asm volatile("mbarrier.arrive.shared.b64 _, [%0];" :: "r"(addr) : "memory")

#define MBARRIER_WAIT_PARITY(addr, parity) do { \
    uint32_t _m = (addr); uint32_t _p = (parity); uint32_t _d; \
    asm volatile("{\n\t.reg .pred p;\n\t" \
        "mbarrier.try_wait.parity.acquire.cta.shared::cta.b64 p, [%1], %2;\n\t" \
        "selp.b32 %0, 1, 0, p;\n\t}" : "=r"(_d) : "r"(_m), "r"(_p) : "memory"); \
    if (!_d) { \
        asm volatile("{\n\t.reg .pred P1;\n\t" \
            "WL_%=:\n\t" \
            "mbarrier.try_wait.parity.acquire.cta.shared::cta.b64 P1, [%0], %1, 0x989680;\n\t" \
            "@P1 bra.uni WD_%=;\n\t" \
            "bra.uni WL_%=;\n\t" \
            "WD_%=:\n\t}" :: "r"(_m), "r"(_p) : "memory"); \
    } \
} while (0)

__device__ __forceinline__ void bulk_g2s(uint32_t dst, const void* src,
                                         uint32_t bytes, uint32_t mbar) {
    asm volatile(
        "cp.async.bulk.shared::cluster.global.mbarrier::complete_tx::bytes "
        "[%0], [%1], %2, [%3];"
        :: "r"(dst), "l"(src), "r"(bytes), "r"(mbar) : "memory");
}

__device__ __forceinline__ void ldsm_x4(uint32_t* r, uint32_t addr) {
    asm volatile("ldmatrix.sync.aligned.m8n8.x4.shared.b16 {%0,%1,%2,%3}, [%4];"
                 : "=r"(r[0]), "=r"(r[1]), "=r"(r[2]), "=r"(r[3]) : "r"(addr));
}
__device__ __forceinline__ void ldsm_x2(uint32_t* r, uint32_t addr) {
    asm volatile("ldmatrix.sync.aligned.m8n8.x2.shared.b16 {%0,%1}, [%2];"
                 : "=r"(r[0]), "=r"(r[1]) : "r"(addr));
}
__device__ __forceinline__ void mma16816(float* d, const uint32_t* a,
                                         const uint32_t* b) {
    asm volatile(
        "mma.sync.aligned.m16n8k16.row.col.f32.bf16.bf16.f32 "
        "{%0,%1,%2,%3}, {%4,%5,%6,%7}, {%8,%9}, {%0,%1,%2,%3};"
        : "+f"(d[0]), "+f"(d[1]), "+f"(d[2]), "+f"(d[3])
        : "r"(a[0]), "r"(a[1]), "r"(a[2]), "r"(a[3]), "r"(b[0]), "r"(b[1]));
}

// ---------------------------------------------------------------------------
// Kernel 0 (merged prep):
//  blocks 0..511   : split x into bf16 hi/lo tiles (128x64, SW128-pre-swizzled)
//  blocks 512..639 : split W1 likewise
//  blocks 640..767 : s[t] = sum_n (x@W2^T + b2)[t,n] * (x@W3^T + b3)[t,n]
// ---------------------------------------------------------------------------
__global__ __launch_bounds__(256) void prep_kernel(
    const float* __restrict__ X, const float* __restrict__ W,
    const float* __restrict__ W2, const float* __restrict__ b2,
    const float* __restrict__ W3, const float* __restrict__ b3)
{
    const int bid = blockIdx.x;
    const int tid = threadIdx.x;

    if (bid < 640) {
        // ------------- convert part -------------
        const float* src;
        uint4 *dhi, *dlo;
        if (bid < 512) {
            int mb = bid >> 4, kb = bid & 15;
            src = X + (size_t)mb * 128 * DDIM + kb * 64;
            dhi = g_xhi + (size_t)bid * 1024;
            dlo = g_xlo + (size_t)bid * 1024;
        } else {
            int t = bid - 512;
            int nb = t >> 4, kb = t & 15;
            src = W + (size_t)nb * 128 * DDIM + kb * 64;
            dhi = g_whi + (size_t)t * 1024;
            dlo = g_wlo + (size_t)t * 1024;
        }
        #pragma unroll
        for (int it = 0; it < 4; ++it) {
            int c = tid + it * 256;
            int row = c >> 3, c8 = c & 7;
            const float* p = src + (size_t)row * DDIM + c8 * 8;
            float4 v0 = *reinterpret_cast<const float4*>(p);
            float4 v1 = *reinterpret_cast<const float4*>(p + 4);
            float v[8] = {v0.x, v0.y, v0.z, v0.w, v1.x, v1.y, v1.z, v1.w};
            uint32_t ph[4], pl[4];
            #pragma unroll
            for (int i = 0; i < 4; ++i) {
                __nv_bfloat16 h0 = __float2bfloat16_rn(v[2 * i]);
                __nv_bfloat16 h1 = __float2bfloat16_rn(v[2 * i + 1]);
                __nv_bfloat16 l0 = __float2bfloat16_rn(v[2 * i]     - __bfloat162float(h0));
                __nv_bfloat16 l1 = __float2bfloat16_rn(v[2 * i + 1] - __bfloat162float(h1));
                ph[i] = (uint32_t)__bfloat16_as_ushort(h0) |
                        ((uint32_t)__bfloat16_as_ushort(h1) << 16);
                pl[i] = (uint32_t)__bfloat16_as_ushort(l0) |
                        ((uint32_t)__bfloat16_as_ushort(l1) << 16);
            }
            uint32_t off = (uint32_t)(row * 128 + c8 * 16);
            off ^= ((off >> 3) & 0x70);   // SW128 swizzle, pre-applied
            dhi[off >> 4] = make_uint4(ph[0], ph[1], ph[2], ph[3]);
            dlo[off >> 4] = make_uint4(pl[0], pl[1], pl[2], pl[3]);
        }
        return;
    }

    // ------------- s part -------------
    __shared__ float sx[32][68];
    __shared__ float sw[32][64];
    __shared__ float sout[32][33];

    const int t0  = (bid - 640) * 32;
    const int tok = tid & 31;
    const int g   = tid >> 5;

    float acc[4] = {0.f, 0.f, 0.f, 0.f};

    for (int k0 = 0; k0 < DDIM; k0 += 64) {
        for (int f4 = tid; f4 < 512; f4 += 256) {
            int tk = f4 >> 4, c4 = f4 & 15;
            *reinterpret_cast<float4*>(&sx[tk][c4 * 4]) =
                *reinterpret_cast<const float4*>(
                    &X[(size_t)(t0 + tk) * DDIM + k0 + c4 * 4]);
        }
        for (int f4 = tid; f4 < 512; f4 += 256) {
            int n = f4 >> 4, c4 = f4 & 15;
            const float* src = (n < 16) ? &W2[(size_t)n * DDIM]
                                        : &W3[(size_t)(n - 16) * DDIM];
            *reinterpret_cast<float4*>(&sw[n][c4 * 4]) =
                *reinterpret_cast<const float4*>(&src[k0 + c4 * 4]);
        }
        __syncthreads();
        #pragma unroll
        for (int k4 = 0; k4 < 16; ++k4) {
            float4 xv = *reinterpret_cast<const float4*>(&sx[tok][k4 * 4]);
            #pragma unroll
            for (int j = 0; j < 4; ++j) {
                float4 wv = *reinterpret_cast<const float4*>(&sw[g * 4 + j][k4 * 4]);
                acc[j] += xv.x * wv.x + xv.y * wv.y + xv.z * wv.z + xv.w * wv.w;
            }
        }
        __syncthreads();
    }

    #pragma unroll
    for (int j = 0; j < 4; ++j) sout[tok][g * 4 + j] = acc[j];
    __syncthreads();

    if (tid < 32) {
        float s = 0.f;
        #pragma unroll
        for (int n = 0; n < 16; ++n)
            s += (sout[tid][n] + b2[n]) * (sout[tid][16 + n] + b3[n]);
        g_s[t0 + tid] = s;
    }
}

// ---------------------------------------------------------------------------
// Kernel 1: mma.sync bf16x3 GEMM, cp.async.bulk-fed, fused epilogue.
//   D = xhi@whi^T + xhi@wlo^T + xlo@whi^T; y = x * softplus(D + b1) * s
// BM=BN=128, BK=64, 3-stage bulk pipeline, 288 threads:
//   warps 0-7 compute (64x32 tiles), warp 8 = producer.
// Register double-buffered fragments: ldmatrix for step kk+1 issues BEFORE
// the 48 HMMAs of step kk (volatile order), hiding LDSM latency.
// ---------------------------------------------------------------------------
#define NKT 16                    // 1024 / 64
#define STAGES 3
#define PART_B 16384              // one 128x64 bf16 tile
#define STAGE_B (4 * PART_B)      // Ahi, Alo, Bhi, Blo = 64KB
#define GEMM_SMEM (STAGES * STAGE_B)   // 196608

__global__ __launch_bounds__(288, 1) void gemm_kernel(
    const float* __restrict__ x,
    const float* __restrict__ b1,
    float* __restrict__ y)
{
    extern __shared__ __align__(1024) char smem[];
    __shared__ __align__(8) uint64_t mbar[2 * STAGES];  // full[0..2], empty[0..2]

    const uint32_t sdyn = smem_u32(smem);
    const uint32_t sFull  = smem_u32(&mbar[0]);
    const uint32_t sEmpty = smem_u32(&mbar[STAGES]);

    const int tid  = threadIdx.x;
    const int wid  = tid >> 5;
    const int lane = tid & 31;
    const int nb = blockIdx.x;          // 0..7
    const int mb = blockIdx.y;          // 0..31
    const int rbase = mb * 128;
    const int cbase = nb * 128;

    if (tid == 0) {
        #pragma unroll
        for (int s = 0; s < STAGES; ++s) {
            MBARRIER_INIT(sFull  + s * 8, 1);
            MBARRIER_INIT(sEmpty + s * 8, 8);
        }
    }
    __syncthreads();

    if (wid == 8) {
        // ---------------- producer ----------------
        if (lane == 0) {
            const char* xhiB = (const char*)g_xhi;
            const char* xloB = (const char*)g_xlo;
            const char* whiB = (const char*)g_whi;
            const char* wloB = (const char*)g_wlo;
            int st = 0, ph = 1;
            for (int kt = 0; kt < NKT; ++kt) {
                MBARRIER_WAIT_PARITY(sEmpty + st * 8, ph);
                uint32_t fb = sFull + st * 8;
                MBARRIER_EXPECT_TX(fb, STAGE_B);
                uint32_t sb = sdyn + st * STAGE_B;
                size_t ax = ((size_t)(mb * NKT + kt)) * PART_B;
                size_t bw = ((size_t)(nb * NKT + kt)) * PART_B;
                bulk_g2s(sb + 0 * PART_B, xhiB + ax, PART_B, fb);
                bulk_g2s(sb + 1 * PART_B, xloB + ax, PART_B, fb);
                bulk_g2s(sb + 2 * PART_B, whiB + bw, PART_B, fb);
                bulk_g2s(sb + 3 * PART_B, wloB + bw, PART_B, fb);
                if (++st == STAGES) { st = 0; ph ^= 1; }
            }
        }
        return;
    }

    // ---------------- consumers (warps 0-7) ----------------
    const int warp_m = wid & 1;
    const int warp_n = wid >> 1;

    float acc[4][4][4];
    #pragma unroll
    for (int i = 0; i < 4; ++i)
        #pragma unroll
        for (int j = 0; j < 4; ++j)
            #pragma unroll
            for (int e = 0; e < 4; ++e)
                acc[i][j][e] = 0.f;

    // per-thread frag row bases + swizzle keys
    uint32_t aRow[4], aSw[4], bRow[4], bSw[4];
    #pragma unroll
    for (int i = 0; i < 4; ++i) {
        int r = warp_m * 64 + i * 16 + (lane & 15);
        aRow[i] = (uint32_t)r * 128;
        aSw[i]  = (uint32_t)(r & 7);
    }
    #pragma unroll
    for (int j = 0; j < 4; ++j) {
        int r = warp_n * 32 + j * 8 + (lane & 7);
        bRow[j] = (uint32_t)r * 128;
        bSw[j]  = (uint32_t)(r & 7);
    }
    const uint32_t ac0 = (uint32_t)(lane >> 4);        // 0/1
    const uint32_t bc0 = (uint32_t)((lane >> 3) & 1);  // 0/1

    // double-buffered fragments
    uint32_t Ah[2][4][4], Al[2][4][4], Bh[2][4][2], Bl[2][4][2];

    #define LOAD_FRAGS(bf, sb, kk) do {                                   \
        const uint32_t _ca = (uint32_t)(kk) * 2 + ac0;                    \
        const uint32_t _cb = (uint32_t)(kk) * 2 + bc0;                    \
        _Pragma("unroll")                                                 \
        for (int _i = 0; _i < 4; ++_i) {                                  \
            uint32_t _off = aRow[_i] + ((_ca ^ aSw[_i]) << 4);            \
            ldsm_x4(Ah[bf][_i], (sb) + 0 * PART_B + _off);                \
            ldsm_x4(Al[bf][_i], (sb) + 1 * PART_B + _off);                \
        }                                                                 \
        _Pragma("unroll")                                                 \
        for (int _j = 0; _j < 4; ++_j) {                                  \
            uint32_t _off = bRow[_j] + ((_cb ^ bSw[_j]) << 4);            \
            ldsm_x2(Bh[bf][_j], (sb) + 2 * PART_B + _off);                \
            ldsm_x2(Bl[bf][_j], (sb) + 3 * PART_B + _off);                \
        }                                                                 \
    } while (0)

    #define DO_MMAS(bf) do {                                              \
        _Pragma("unroll")                                                  \
        for (int _i = 0; _i < 4; ++_i)                                     \
            _Pragma("unroll")                                              \
            for (int _j = 0; _j < 4; ++_j)                                 \
                mma16816(acc[_i][_j], Ah[bf][_i], Bh[bf][_j]);             \
        _Pragma("unroll")                                                  \
        for (int _i = 0; _i < 4; ++_i)                                     \
            _Pragma("unroll")                                              \
            for (int _j = 0; _j < 4; ++_j)                                 \
                mma16816(acc[_i][_j], Ah[bf][_i], Bl[bf][_j]);             \
        _Pragma("unroll")                                                  \
        for (int _i = 0; _i < 4; ++_i)                                     \
            _Pragma("unroll")                                              \
            for (int _j = 0; _j < 4; ++_j)                                 \
                mma16816(acc[_i][_j], Al[bf][_i], Bh[bf][_j]);             \
    } while (0)

    int st = 0, ph = 0;
    MBARRIER_WAIT_PARITY(sFull + 0, 0);
    LOAD_FRAGS(0, sdyn, 0);          // preload kk=0 of stage 0

    for (int kt = 0; kt < NKT; ++kt) {
        const uint32_t sb = sdyn + st * STAGE_B;
        #pragma unroll
        for (int kk = 0; kk < 4; ++kk) {
            const int cur = kk & 1;
            if (kk < 3) LOAD_FRAGS(cur ^ 1, sb, kk + 1);   // prefetch next step
            DO_MMAS(cur);
        }
        if (lane == 0) MBARRIER_ARRIVE(sEmpty + st * 8);
        if (++st == STAGES) { st = 0; ph ^= 1; }
        if (kt + 1 < NKT) {
            MBARRIER_WAIT_PARITY(sFull + st * 8, ph);
            LOAD_FRAGS(0, sdyn + st * STAGE_B, 0);         // preload next kt
        }
    }

    // epilogue: y = x * softplus(acc + b1) * s
    #pragma unroll
    for (int i = 0; i < 4; ++i) {
        const int r0 = rbase + warp_m * 64 + i * 16 + (lane >> 2);
        const int r1 = r0 + 8;
        const float s0 = g_s[r0], s1 = g_s[r1];
        #pragma unroll
        for (int j = 0; j < 4; ++j) {
            const int c = cbase + warp_n * 32 + j * 8 + (lane & 3) * 2;
            float2 bv = *reinterpret_cast<const float2*>(b1 + c);
            float2 x0 = *reinterpret_cast<const float2*>(x + (size_t)r0 * DDIM + c);
            float2 x1 = *reinterpret_cast<const float2*>(x + (size_t)r1 * DDIM + c);
            float2 o0, o1;
            o0.x = x0.x * softplusf(acc[i][j][0] + bv.x) * s0;
            o0.y = x0.y * softplusf(acc[i][j][1] + bv.y) * s0;
            o1.x = x1.x * softplusf(acc[i][j][2] + bv.x) * s1;
            o1.y = x1.y * softplusf(acc[i][j][3] + bv.y) * s1;
            *reinterpret_cast<float2*>(y + (size_t)r0 * DDIM + c) = o0;
            *reinterpret_cast<float2*>(y + (size_t)r1 * DDIM + c) = o1;
        }
    }
}

// ---------------------------------------------------------------------------
extern "C" void kernel_launch(void* const* d_in, const int* in_sizes, int n_in,
                              void* d_out, int out_size)
{
    const float* x  = (const float*)d_in[0];
    const float* W1 = (const float*)d_in[1];
    const float* b1 = (const float*)d_in[2];
    const float* W2 = (const float*)d_in[3];
    const float* b2 = (const float*)d_in[4];
    const float* W3 = (const float*)d_in[5];
    const float* b3 = (const float*)d_in[6];
    // d_in[7] = A is mathematically dead (multiplies zero-initialized h).
    float* y = (float*)d_out;

    cudaFuncSetAttribute(gemm_kernel,
                         cudaFuncAttributeMaxDynamicSharedMemorySize, GEMM_SMEM);

    prep_kernel<<<768, 256>>>(x, W1, W2, b2, W3, b3);

    dim3 grid(DDIM / 128, TOKENS / 128);   // (8, 32)
    gemm_kernel<<<grid, 288, GEMM_SMEM>>>(x, b1, y);
}

// round 8
// speedup vs baseline: 1.0657x; 1.0657x over previous
#include <cuda_runtime.h>
#include <cuda_bf16.h>
#include <math.h>
#include <stdint.h>

#define TOKENS 4096
#define DDIM   1024

// ---------------------------------------------------------------------------
// scratch (__device__ globals; no cudaMalloc allowed)
// x/W1 hi+lo bf16, PRE-TILED into 16KB tiles (128 rows x 64 cols, SW128-swizzled)
// x: 32 mb x 16 kt = 512 tiles;  W1: 8 nb x 16 kt = 128 tiles
// ---------------------------------------------------------------------------
__device__ float g_s[TOKENS];
__device__ __align__(1024) uint4 g_xhi[512 * 1024];
__device__ __align__(1024) uint4 g_xlo[512 * 1024];
__device__ __align__(1024) uint4 g_whi[128 * 1024];
__device__ __align__(1024) uint4 g_wlo[128 * 1024];

__device__ __forceinline__ float softplusf(float z) {
    if (z > 20.0f) return z;
    return log1pf(expf(z));
}

__device__ __forceinline__ uint32_t smem_u32(const void* p) {
    uint32_t a;
    asm("{ .reg .u64 t; cvta.to.shared.u64 t, %1; cvt.u32.u64 %0, t; }"
        : "=r"(a) : "l"(p));
    return a;
}

#define MBARRIER_INIT(addr, cnt) \
    asm volatile("mbarrier.init.shared.b64 [%0], %1;" :: "r"(addr), "r"(cnt) : "memory")
#define MBARRIER_EXPECT_TX(addr, bytes) \
    asm volatile("mbarrier.arrive.expect_tx.shared.b64 _, [%0], %1;" \
        :: "r"(addr), "r"(bytes) : "memory")
#define MBARRIER_ARRIVE(addr) \
    asm volatile("mbarrier.arrive.shared.b64 _, [%0];" :: "r"(addr) : "memory")

#define MBARRIER_WAIT_PARITY(addr, parity) do { \
    uint32_t _m = (addr); uint32_t _p = (parity); uint32_t _d; \
    asm volatile("{\n\t.reg .pred p;\n\t" \
        "mbarrier.try_wait.parity.acquire.cta.shared::cta.b64 p, [%1], %2;\n\t" \
        "selp.b32 %0, 1, 0, p;\n\t}" : "=r"(_d) : "r"(_m), "r"(_p) : "memory"); \
    if (!_d) { \
        asm volatile("{\n\t.reg .pred P1;\n\t" \
            "WL_%=:\n\t" \
            "mbarrier.try_wait.parity.acquire.cta.shared::cta.b64 P1, [%0], %1, 0x989680;\n\t" \
            "@P1 bra.uni WD_%=;\n\t" \
            "bra.uni WL_%=;\n\t" \
            "WD_%=:\n\t}" :: "r"(_m), "r"(_p) : "memory"); \
    } \
} while (0)

__device__ __forceinline__ void bulk_g2s(uint32_t dst, const void* src,
                                         uint32_t bytes, uint32_t mbar) {
    asm volatile(
        "cp.async.bulk.shared::cluster.global.mbarrier::complete_tx::bytes "
        "[%0], [%1], %2, [%3];"
        :: "r"(dst), "l"(src), "r"(bytes), "r"(mbar) : "memory");
}

__device__ __forceinline__ void ldsm_x4(uint32_t* r, uint32_t addr) {
    asm volatile("ldmatrix.sync.aligned.m8n8.x4.shared.b16 {%0,%1,%2,%3}, [%4];"
                 : "=r"(r[0]), "=r"(r[1]), "=r"(r[2]), "=r"(r[3]) : "r"(addr));
}
__device__ __forceinline__ void mma16816(float* d, const uint32_t* a,
                                         const uint32_t* b) {
    asm volatile(
        "mma.sync.aligned.m16n8k16.row.col.f32.bf16.bf16.f32 "
        "{%0,%1,%2,%3}, {%4,%5,%6,%7}, {%8,%9}, {%0,%1,%2,%3};"
        : "+f"(d[0]), "+f"(d[1]), "+f"(d[2]), "+f"(d[3])
        : "r"(a[0]), "r"(a[1]), "r"(a[2]), "r"(a[3]), "r"(b[0]), "r"(b[1]));
}

// ---------------------------------------------------------------------------
// Kernel 0 (merged prep):
//  blocks 0..511   : split x into bf16 hi/lo tiles (128x64, SW128-pre-swizzled)
//  blocks 512..639 : split W1 likewise
//  blocks 640..767 : s[t] = sum_n (x@W2^T + b2)[t,n] * (x@W3^T + b3)[t,n]
// ---------------------------------------------------------------------------
__global__ __launch_bounds__(256) void prep_kernel(
    const float* __restrict__ X, const float* __restrict__ W,
    const float* __restrict__ W2, const float* __restrict__ b2,
    const float* __restrict__ W3, const float* __restrict__ b3)
{
    const int bid = blockIdx.x;
    const int tid = threadIdx.x;

    if (bid < 640) {
        // ------------- convert part -------------
        const float* src;
        uint4 *dhi, *dlo;
        if (bid < 512) {
            int mb = bid >> 4, kb = bid & 15;
            src = X + (size_t)mb * 128 * DDIM + kb * 64;
            dhi = g_xhi + (size_t)bid * 1024;
            dlo = g_xlo + (size_t)bid * 1024;
        } else {
            int t = bid - 512;
            int nb = t >> 4, kb = t & 15;
            src = W + (size_t)nb * 128 * DDIM + kb * 64;
            dhi = g_whi + (size_t)t * 1024;
            dlo = g_wlo + (size_t)t * 1024;
        }
        #pragma unroll
        for (int it = 0; it < 4; ++it) {
            int c = tid + it * 256;
            int row = c >> 3, c8 = c & 7;
            const float* p = src + (size_t)row * DDIM + c8 * 8;
            float4 v0 = *reinterpret_cast<const float4*>(p);
            float4 v1 = *reinterpret_cast<const float4*>(p + 4);
            float v[8] = {v0.x, v0.y, v0.z, v0.w, v1.x, v1.y, v1.z, v1.w};
            uint32_t ph[4], pl[4];
            #pragma unroll
            for (int i = 0; i < 4; ++i) {
                __nv_bfloat16 h0 = __float2bfloat16_rn(v[2 * i]);
                __nv_bfloat16 h1 = __float2bfloat16_rn(v[2 * i + 1]);
                __nv_bfloat16 l0 = __float2bfloat16_rn(v[2 * i]     - __bfloat162float(h0));
                __nv_bfloat16 l1 = __float2bfloat16_rn(v[2 * i + 1] - __bfloat162float(h1));
                ph[i] = (uint32_t)__bfloat16_as_ushort(h0) |
                        ((uint32_t)__bfloat16_as_ushort(h1) << 16);
                pl[i] = (uint32_t)__bfloat16_as_ushort(l0) |
                        ((uint32_t)__bfloat16_as_ushort(l1) << 16);
            }
            uint32_t off = (uint32_t)(row * 128 + c8 * 16);
            off ^= ((off >> 3) & 0x70);   // SW128 swizzle, pre-applied
            dhi[off >> 4] = make_uint4(ph[0], ph[1], ph[2], ph[3]);
            dlo[off >> 4] = make_uint4(pl[0], pl[1], pl[2], pl[3]);
        }
        return;
    }

    // ------------- s part -------------
    __shared__ float sx[32][68];
    __shared__ float sw[32][64];
    __shared__ float sout[32][33];

    const int t0  = (bid - 640) * 32;
    const int tok = tid & 31;
    const int g   = tid >> 5;

    float acc[4] = {0.f, 0.f, 0.f, 0.f};

    for (int k0 = 0; k0 < DDIM; k0 += 64) {
        for (int f4 = tid; f4 < 512; f4 += 256) {
            int tk = f4 >> 4, c4 = f4 & 15;
            *reinterpret_cast<float4*>(&sx[tk][c4 * 4]) =
                *reinterpret_cast<const float4*>(
                    &X[(size_t)(t0 + tk) * DDIM + k0 + c4 * 4]);
        }
        for (int f4 = tid; f4 < 512; f4 += 256) {
            int n = f4 >> 4, c4 = f4 & 15;
            const float* src = (n < 16) ? &W2[(size_t)n * DDIM]
                                        : &W3[(size_t)(n - 16) * DDIM];
            *reinterpret_cast<float4*>(&sw[n][c4 * 4]) =
                *reinterpret_cast<const float4*>(&src[k0 + c4 * 4]);
        }
        __syncthreads();
        #pragma unroll
        for (int k4 = 0; k4 < 16; ++k4) {
            float4 xv = *reinterpret_cast<const float4*>(&sx[tok][k4 * 4]);
            #pragma unroll
            for (int j = 0; j < 4; ++j) {
                float4 wv = *reinterpret_cast<const float4*>(&sw[g * 4 + j][k4 * 4]);
                acc[j] += xv.x * wv.x + xv.y * wv.y + xv.z * wv.z + xv.w * wv.w;
            }
        }
        __syncthreads();
    }

    #pragma unroll
    for (int j = 0; j < 4; ++j) sout[tok][g * 4 + j] = acc[j];
    __syncthreads();

    if (tid < 32) {
        float s = 0.f;
        #pragma unroll
        for (int n = 0; n < 16; ++n)
            s += (sout[tid][n] + b2[n]) * (sout[tid][16 + n] + b3[n]);
        g_s[t0 + tid] = s;
    }
}

// ---------------------------------------------------------------------------
// Kernel 1: mma.sync bf16x3 GEMM, cp.async.bulk-fed, fused epilogue.
//   D = xhi@whi^T + xhi@wlo^T + xlo@whi^T; y = x * softplus(D + b1) * s
// BM=BN=128, BK=64, 3-stage bulk pipeline, 544 threads:
//   warps 0-15 compute (32x32 tiles, 4 warps/SMSP for TLP), warp 16 = producer.
// ---------------------------------------------------------------------------
#define NKT 16                    // 1024 / 64
#define STAGES 3
#define PART_B 16384              // one 128x64 bf16 tile
#define STAGE_B (4 * PART_B)      // Ahi, Alo, Bhi, Blo = 64KB
#define GEMM_SMEM (STAGES * STAGE_B)   // 196608

__global__ __launch_bounds__(544, 1) void gemm_kernel(
    const float* __restrict__ x,
    const float* __restrict__ b1,
    float* __restrict__ y)
{
    extern __shared__ __align__(1024) char smem[];
    __shared__ __align__(8) uint64_t mbar[2 * STAGES];  // full[0..2], empty[0..2]

    const uint32_t sdyn = smem_u32(smem);
    const uint32_t sFull  = smem_u32(&mbar[0]);
    const uint32_t sEmpty = smem_u32(&mbar[STAGES]);

    const int tid  = threadIdx.x;
    const int wid  = tid >> 5;
    const int lane = tid & 31;
    const int nb = blockIdx.x;          // 0..7
    const int mb = blockIdx.y;          // 0..31
    const int rbase = mb * 128;
    const int cbase = nb * 128;

    if (tid == 0) {
        #pragma unroll
        for (int s = 0; s < STAGES; ++s) {
            MBARRIER_INIT(sFull  + s * 8, 1);
            MBARRIER_INIT(sEmpty + s * 8, 16);
        }
    }
    __syncthreads();

    if (wid == 16) {
        // ---------------- producer ----------------
        if (lane == 0) {
            const char* xhiB = (const char*)g_xhi;
            const char* xloB = (const char*)g_xlo;
            const char* whiB = (const char*)g_whi;
            const char* wloB = (const char*)g_wlo;
            int st = 0, ph = 1;
            for (int kt = 0; kt < NKT; ++kt) {
                MBARRIER_WAIT_PARITY(sEmpty + st * 8, ph);
                uint32_t fb = sFull + st * 8;
                MBARRIER_EXPECT_TX(fb, STAGE_B);
                uint32_t sb = sdyn + st * STAGE_B;
                size_t ax = ((size_t)(mb * NKT + kt)) * PART_B;
                size_t bw = ((size_t)(nb * NKT + kt)) * PART_B;
                bulk_g2s(sb + 0 * PART_B, xhiB + ax, PART_B, fb);
                bulk_g2s(sb + 1 * PART_B, xloB + ax, PART_B, fb);
                bulk_g2s(sb + 2 * PART_B, whiB + bw, PART_B, fb);
                bulk_g2s(sb + 3 * PART_B, wloB + bw, PART_B, fb);
                if (++st == STAGES) { st = 0; ph ^= 1; }
            }
        }
        return;
    }

    // ---------------- consumers (warps 0-15), 32x32 warp tiles ----------------
    const int warp_m = wid & 3;    // row group: 32 rows
    const int warp_n = wid >> 2;   // col group: 32 cols

    float acc[2][4][4];
    #pragma unroll
    for (int i = 0; i < 2; ++i)
        #pragma unroll
        for (int j = 0; j < 4; ++j)
            #pragma unroll
            for (int e = 0; e < 4; ++e)
                acc[i][j][e] = 0.f;

    // A frag addresses: i in {0,1} (two m16 tiles)
    uint32_t aRow[2], aSw[2];
    #pragma unroll
    for (int i = 0; i < 2; ++i) {
        int r = warp_m * 32 + i * 16 + (lane & 15);
        aRow[i] = (uint32_t)r * 128;
        aSw[i]  = (uint32_t)(r & 7);
    }
    // B frag addresses via ldsm_x4: jj in {0,1}, each yields 2 n8 frags
    // lane->row: +8 for lanes 16-31 (second n8); lane bit3 -> k8 half
    uint32_t bRow[2], bSw[2];
    #pragma unroll
    for (int jj = 0; jj < 2; ++jj) {
        int r = warp_n * 32 + jj * 16 + (lane & 7) + ((lane >> 4) & 1) * 8;
        bRow[jj] = (uint32_t)r * 128;
        bSw[jj]  = (uint32_t)(r & 7);
    }
    const uint32_t ac0 = (uint32_t)(lane >> 4);        // 0/1 (k8 half for A)
    const uint32_t bc0 = (uint32_t)((lane >> 3) & 1);  // 0/1 (k8 half for B)

    int st = 0, ph = 0;
    for (int kt = 0; kt < NKT; ++kt) {
        MBARRIER_WAIT_PARITY(sFull + st * 8, ph);
        const uint32_t sb = sdyn + st * STAGE_B;
        const uint32_t ah = sb + 0 * PART_B;
        const uint32_t al = sb + 1 * PART_B;
        const uint32_t bh = sb + 2 * PART_B;
        const uint32_t bl = sb + 3 * PART_B;

        #pragma unroll
        for (int kk = 0; kk < 4; ++kk) {       // four k16 steps of BK=64
            uint32_t Ah[2][4], Al[2][4], Bh[2][4], Bl[2][4];
            const uint32_t ca = kk * 2 + ac0;
            const uint32_t cb = kk * 2 + bc0;
            #pragma unroll
            for (int i = 0; i < 2; ++i) {
                uint32_t off = aRow[i] + ((ca ^ aSw[i]) << 4);
                ldsm_x4(Ah[i], ah + off);
                ldsm_x4(Al[i], al + off);
            }
            #pragma unroll
            for (int jj = 0; jj < 2; ++jj) {
                uint32_t off = bRow[jj] + ((cb ^ bSw[jj]) << 4);
                ldsm_x4(Bh[jj], bh + off);
                ldsm_x4(Bl[jj], bl + off);
            }
            // term-major: 8 MMAs per term, reuse distance 8
            #pragma unroll
            for (int i = 0; i < 2; ++i)
                #pragma unroll
                for (int j = 0; j < 4; ++j)
                    mma16816(acc[i][j], Ah[i], &Bh[j >> 1][(j & 1) * 2]);
            #pragma unroll
            for (int i = 0; i < 2; ++i)
                #pragma unroll
                for (int j = 0; j < 4; ++j)
                    mma16816(acc[i][j], Ah[i], &Bl[j >> 1][(j & 1) * 2]);
            #pragma unroll
            for (int i = 0; i < 2; ++i)
                #pragma unroll
                for (int j = 0; j < 4; ++j)
                    mma16816(acc[i][j], Al[i], &Bh[j >> 1][(j & 1) * 2]);
        }
        if (lane == 0) MBARRIER_ARRIVE(sEmpty + st * 8);
        if (++st == STAGES) { st = 0; ph ^= 1; }
    }

    // epilogue: y = x * softplus(acc + b1) * s
    #pragma unroll
    for (int i = 0; i < 2; ++i) {
        const int r0 = rbase + warp_m * 32 + i * 16 + (lane >> 2);
        const int r1 = r0 + 8;
        const float s0 = g_s[r0], s1 = g_s[r1];
        #pragma unroll
        for (int j = 0; j < 4; ++j) {
            const int c = cbase + warp_n * 32 + j * 8 + (lane & 3) * 2;
            float2 bv = *reinterpret_cast<const float2*>(b1 + c);
            float2 x0 = *reinterpret_cast<const float2*>(x + (size_t)r0 * DDIM + c);
            float2 x1 = *reinterpret_cast<const float2*>(x + (size_t)r1 * DDIM + c);
            float2 o0, o1;
            o0.x = x0.x * softplusf(acc[i][j][0] + bv.x) * s0;
            o0.y = x0.y * softplusf(acc[i][j][1] + bv.y) * s0;
            o1.x = x1.x * softplusf(acc[i][j][2] + bv.x) * s1;
            o1.y = x1.y * softplusf(acc[i][j][3] + bv.y) * s1;
            *reinterpret_cast<float2*>(y + (size_t)r0 * DDIM + c) = o0;
            *reinterpret_cast<float2*>(y + (size_t)r1 * DDIM + c) = o1;
        }
    }
}

// ---------------------------------------------------------------------------
extern "C" void kernel_launch(void* const* d_in, const int* in_sizes, int n_in,
                              void* d_out, int out_size)
{
    const float* x  = (const float*)d_in[0];
    const float* W1 = (const float*)d_in[1];
    const float* b1 = (const float*)d_in[2];
    const float* W2 = (const float*)d_in[3];
    const float* b2 = (const float*)d_in[4];
    const float* W3 = (const float*)d_in[5];
    const float* b3 = (const float*)d_in[6];
    // d_in[7] = A is mathematically dead (multiplies zero-initialized h).
    float* y = (float*)d_out;

    cudaFuncSetAttribute(gemm_kernel,
                         cudaFuncAttributeMaxDynamicSharedMemorySize, GEMM_SMEM);

    prep_kernel<<<768, 256>>>(x, W1, W2, b2, W3, b3);

    dim3 grid(DDIM / 128, TOKENS / 128);   // (8, 32)
    gemm_kernel<<<grid, 544, GEMM_SMEM>>>(x, b1, y);
}

// round 9
// speedup vs baseline: 1.0769x; 1.0105x over previous
#include <cuda_runtime.h>
#include <cuda_bf16.h>
#include <math.h>
#include <stdint.h>

#define TOKENS 4096
#define DDIM   1024

// ---------------------------------------------------------------------------
// scratch (__device__ globals; no cudaMalloc allowed)
// x/W1 hi+lo bf16, PRE-TILED into 16KB tiles (128 rows x 64 cols, SW128-swizzled)
// x: 32 mb x 16 kt = 512 tiles;  W1: 8 nb x 16 kt = 128 tiles
// ---------------------------------------------------------------------------
__device__ float g_s[TOKENS];
__device__ __align__(1024) uint4 g_xhi[512 * 1024];
__device__ __align__(1024) uint4 g_xlo[512 * 1024];
__device__ __align__(1024) uint4 g_whi[128 * 1024];
__device__ __align__(1024) uint4 g_wlo[128 * 1024];

__device__ __forceinline__ float softplusf(float z) {
    if (z > 20.0f) return z;
    return log1pf(expf(z));
}

__device__ __forceinline__ uint32_t smem_u32(const void* p) {
    uint32_t a;
    asm("{ .reg .u64 t; cvta.to.shared.u64 t, %1; cvt.u32.u64 %0, t; }"
        : "=r"(a) : "l"(p));
    return a;
}

#define MBARRIER_INIT(addr, cnt) \
    asm volatile("mbarrier.init.shared.b64 [%0], %1;" :: "r"(addr), "r"(cnt) : "memory")
#define MBARRIER_EXPECT_TX(addr, bytes) \
    asm volatile("mbarrier.arrive.expect_tx.shared.b64 _, [%0], %1;" \
        :: "r"(addr), "r"(bytes) : "memory")
#define MBARRIER_ARRIVE(addr) \
    asm volatile("mbarrier.arrive.shared.b64 _, [%0];" :: "r"(addr) : "memory")

#define MBARRIER_WAIT_PARITY(addr, parity) do { \
    uint32_t _m = (addr); uint32_t _p = (parity); uint32_t _d; \
    asm volatile("{\n\t.reg .pred p;\n\t" \
        "mbarrier.try_wait.parity.acquire.cta.shared::cta.b64 p, [%1], %2;\n\t" \
        "selp.b32 %0, 1, 0, p;\n\t}" : "=r"(_d) : "r"(_m), "r"(_p) : "memory"); \
    if (!_d) { \
        asm volatile("{\n\t.reg .pred P1;\n\t" \
            "WL_%=:\n\t" \
            "mbarrier.try_wait.parity.acquire.cta.shared::cta.b64 P1, [%0], %1, 0x989680;\n\t" \
            "@P1 bra.uni WD_%=;\n\t" \
            "bra.uni WL_%=;\n\t" \
            "WD_%=:\n\t}" :: "r"(_m), "r"(_p) : "memory"); \
    } \
} while (0)

__device__ __forceinline__ void bulk_g2s(uint32_t dst, const void* src,
                                         uint32_t bytes, uint32_t mbar) {
    asm volatile(
        "cp.async.bulk.shared::cluster.global.mbarrier::complete_tx::bytes "
        "[%0], [%1], %2, [%3];"
        :: "r"(dst), "l"(src), "r"(bytes), "r"(mbar) : "memory");
}

__device__ __forceinline__ void ldsm_x4(uint32_t* r, uint32_t addr) {
    asm volatile("ldmatrix.sync.aligned.m8n8.x4.shared.b16 {%0,%1,%2,%3}, [%4];"
                 : "=r"(r[0]), "=r"(r[1]), "=r"(r[2]), "=r"(r[3]) : "r"(addr));
}
__device__ __forceinline__ void mma16816(float* d, const uint32_t* a,
                                         const uint32_t* b) {
    asm volatile(
        "mma.sync.aligned.m16n8k16.row.col.f32.bf16.bf16.f32 "
        "{%0,%1,%2,%3}, {%4,%5,%6,%7}, {%8,%9}, {%0,%1,%2,%3};"
        : "+f"(d[0]), "+f"(d[1]), "+f"(d[2]), "+f"(d[3])
        : "r"(a[0]), "r"(a[1]), "r"(a[2]), "r"(a[3]), "r"(b[0]), "r"(b[1]));
}

// ---------------------------------------------------------------------------
// Kernel 0 (merged prep) — s blocks FIRST so the latency-bound s work starts
// in wave 1 and overlaps with the BW-bound convert blocks:
//  blocks 0..127   : s[t] = sum_n (x@W2^T + b2)[t,n] * (x@W3^T + b3)[t,n]
//  blocks 128..639 : split x into bf16 hi/lo tiles (128x64, SW128-pre-swizzled)
//  blocks 640..767 : split W1 likewise
// ---------------------------------------------------------------------------
__global__ __launch_bounds__(256) void prep_kernel(
    const float* __restrict__ X, const float* __restrict__ W,
    const float* __restrict__ W2, const float* __restrict__ b2,
    const float* __restrict__ W3, const float* __restrict__ b3)
{
    const int bid = blockIdx.x;
    const int tid = threadIdx.x;

    if (bid >= 128) {
        // ------------- convert part -------------
        const int cb = bid - 128;
        const float* src;
        uint4 *dhi, *dlo;
        if (cb < 512) {
            int mb = cb >> 4, kb = cb & 15;
            src = X + (size_t)mb * 128 * DDIM + kb * 64;
            dhi = g_xhi + (size_t)cb * 1024;
            dlo = g_xlo + (size_t)cb * 1024;
        } else {
            int t = cb - 512;
            int nb = t >> 4, kb = t & 15;
            src = W + (size_t)nb * 128 * DDIM + kb * 64;
            dhi = g_whi + (size_t)t * 1024;
            dlo = g_wlo + (size_t)t * 1024;
        }
        #pragma unroll
        for (int it = 0; it < 4; ++it) {
            int c = tid + it * 256;
            int row = c >> 3, c8 = c & 7;
            const float* p = src + (size_t)row * DDIM + c8 * 8;
            float4 v0 = *reinterpret_cast<const float4*>(p);
            float4 v1 = *reinterpret_cast<const float4*>(p + 4);
            float v[8] = {v0.x, v0.y, v0.z, v0.w, v1.x, v1.y, v1.z, v1.w};
            uint32_t ph[4], pl[4];
            #pragma unroll
            for (int i = 0; i < 4; ++i) {
                __nv_bfloat16 h0 = __float2bfloat16_rn(v[2 * i]);
                __nv_bfloat16 h1 = __float2bfloat16_rn(v[2 * i + 1]);
                __nv_bfloat16 l0 = __float2bfloat16_rn(v[2 * i]     - __bfloat162float(h0));
                __nv_bfloat16 l1 = __float2bfloat16_rn(v[2 * i + 1] - __bfloat162float(h1));
                ph[i] = (uint32_t)__bfloat16_as_ushort(h0) |
                        ((uint32_t)__bfloat16_as_ushort(h1) << 16);
                pl[i] = (uint32_t)__bfloat16_as_ushort(l0) |
                        ((uint32_t)__bfloat16_as_ushort(l1) << 16);
            }
            uint32_t off = (uint32_t)(row * 128 + c8 * 16);
            off ^= ((off >> 3) & 0x70);   // SW128 swizzle, pre-applied
            dhi[off >> 4] = make_uint4(ph[0], ph[1], ph[2], ph[3]);
            dlo[off >> 4] = make_uint4(pl[0], pl[1], pl[2], pl[3]);
        }
        return;
    }

    // ------------- s part (bids 0..127, wave 1) -------------
    __shared__ float sx[32][68];
    __shared__ float sw[32][64];
    __shared__ float sout[32][33];

    const int t0  = bid * 32;
    const int tok = tid & 31;
    const int g   = tid >> 5;

    float acc[4] = {0.f, 0.f, 0.f, 0.f};

    // register prefetch buffers (hide DRAM latency under FMA work)
    float4 px[2], pw[2];
    {
        int tk = tid >> 3, c4x = tid & 7;          // 32 tok x 8 f4 (first 32 cols)
        px[0] = *reinterpret_cast<const float4*>(
            &X[(size_t)(t0 + tk) * DDIM + c4x * 4]);
        px[1] = *reinterpret_cast<const float4*>(
            &X[(size_t)(t0 + tk) * DDIM + 32 + c4x * 4]);
        int n = tid >> 3, c4w = tid & 7;
        const float* srcw = (n < 16) ? &W2[(size_t)n * DDIM]
                                     : &W3[(size_t)(n - 16) * DDIM];
        pw[0] = *reinterpret_cast<const float4*>(&srcw[c4w * 4]);
        pw[1] = *reinterpret_cast<const float4*>(&srcw[32 + c4w * 4]);
    }

    for (int k0 = 0; k0 < DDIM; k0 += 64) {
        // store prefetched tile to smem
        {
            int tk = tid >> 3, c4 = tid & 7;
            *reinterpret_cast<float4*>(&sx[tk][c4 * 4])      = px[0];
            *reinterpret_cast<float4*>(&sx[tk][32 + c4 * 4]) = px[1];
            *reinterpret_cast<float4*>(&sw[tk][c4 * 4])      = pw[0];
            *reinterpret_cast<float4*>(&sw[tk][32 + c4 * 4]) = pw[1];
        }
        __syncthreads();
        // prefetch next k-tile
        if (k0 + 64 < DDIM) {
            int tk = tid >> 3, c4 = tid & 7;
            px[0] = *reinterpret_cast<const float4*>(
                &X[(size_t)(t0 + tk) * DDIM + k0 + 64 + c4 * 4]);
            px[1] = *reinterpret_cast<const float4*>(
                &X[(size_t)(t0 + tk) * DDIM + k0 + 96 + c4 * 4]);
            int n = tid >> 3;
            const float* srcw = (n < 16) ? &W2[(size_t)n * DDIM]
                                         : &W3[(size_t)(n - 16) * DDIM];
            pw[0] = *reinterpret_cast<const float4*>(&srcw[k0 + 64 + c4 * 4]);
            pw[1] = *reinterpret_cast<const float4*>(&srcw[k0 + 96 + c4 * 4]);
        }
        #pragma unroll
        for (int k4 = 0; k4 < 16; ++k4) {
            float4 xv = *reinterpret_cast<const float4*>(&sx[tok][k4 * 4]);
            #pragma unroll
            for (int j = 0; j < 4; ++j) {
                float4 wv = *reinterpret_cast<const float4*>(&sw[g * 4 + j][k4 * 4]);
                acc[j] += xv.x * wv.x + xv.y * wv.y + xv.z * wv.z + xv.w * wv.w;
            }
        }
        __syncthreads();
    }

    #pragma unroll
    for (int j = 0; j < 4; ++j) sout[tok][g * 4 + j] = acc[j];
    __syncthreads();

    if (tid < 32) {
        float s = 0.f;
        #pragma unroll
        for (int n = 0; n < 16; ++n)
            s += (sout[tid][n] + b2[n]) * (sout[tid][16 + n] + b3[n]);
        g_s[t0 + tid] = s;
    }
}

// ---------------------------------------------------------------------------
// Kernel 1: mma.sync bf16x3 GEMM, cp.async.bulk-fed, fused epilogue.
//   D = xhi@whi^T + xhi@wlo^T + xlo@whi^T; y = x * softplus(D + b1) * s
// BM=BN=128, BK=64, 3-stage bulk pipeline, 544 threads:
//   warps 0-15 compute (32x32 tiles, 4 warps/SMSP for TLP), warp 16 = producer.
// ---------------------------------------------------------------------------
#define NKT 16                    // 1024 / 64
#define STAGES 3
#define PART_B 16384              // one 128x64 bf16 tile
#define STAGE_B (4 * PART_B)      // Ahi, Alo, Bhi, Blo = 64KB
#define GEMM_SMEM (STAGES * STAGE_B)   // 196608

__global__ __launch_bounds__(544, 1) void gemm_kernel(
    const float* __restrict__ x,
    const float* __restrict__ b1,
    float* __restrict__ y)
{
    extern __shared__ __align__(1024) char smem[];
    __shared__ __align__(8) uint64_t mbar[2 * STAGES];  // full[0..2], empty[0..2]

    const uint32_t sdyn = smem_u32(smem);
    const uint32_t sFull  = smem_u32(&mbar[0]);
    const uint32_t sEmpty = smem_u32(&mbar[STAGES]);

    const int tid  = threadIdx.x;
    const int wid  = tid >> 5;
    const int lane = tid & 31;
    const int nb = blockIdx.x;          // 0..7
    const int mb = blockIdx.y;          // 0..31
    const int rbase = mb * 128;
    const int cbase = nb * 128;

    if (tid == 0) {
        #pragma unroll
        for (int s = 0; s < STAGES; ++s) {
            MBARRIER_INIT(sFull  + s * 8, 1);
            MBARRIER_INIT(sEmpty + s * 8, 16);
        }
    }
    __syncthreads();

    if (wid == 16) {
        // ---------------- producer ----------------
        if (lane == 0) {
            const char* xhiB = (const char*)g_xhi;
            const char* xloB = (const char*)g_xlo;
            const char* whiB = (const char*)g_whi;
            const char* wloB = (const char*)g_wlo;
            int st = 0, ph = 1;
            for (int kt = 0; kt < NKT; ++kt) {
                MBARRIER_WAIT_PARITY(sEmpty + st * 8, ph);
                uint32_t fb = sFull + st * 8;
                MBARRIER_EXPECT_TX(fb, STAGE_B);
                uint32_t sb = sdyn + st * STAGE_B;
                size_t ax = ((size_t)(mb * NKT + kt)) * PART_B;
                size_t bw = ((size_t)(nb * NKT + kt)) * PART_B;
                bulk_g2s(sb + 0 * PART_B, xhiB + ax, PART_B, fb);
                bulk_g2s(sb + 1 * PART_B, xloB + ax, PART_B, fb);
                bulk_g2s(sb + 2 * PART_B, whiB + bw, PART_B, fb);
                bulk_g2s(sb + 3 * PART_B, wloB + bw, PART_B, fb);
                if (++st == STAGES) { st = 0; ph ^= 1; }
            }
        }
        return;
    }

    // ---------------- consumers (warps 0-15), 32x32 warp tiles ----------------
    const int warp_m = wid & 3;    // row group: 32 rows
    const int warp_n = wid >> 2;   // col group: 32 cols

    float acc[2][4][4];
    #pragma unroll
    for (int i = 0; i < 2; ++i)
        #pragma unroll
        for (int j = 0; j < 4; ++j)
            #pragma unroll
            for (int e = 0; e < 4; ++e)
                acc[i][j][e] = 0.f;

    // A frag addresses: i in {0,1} (two m16 tiles)
    uint32_t aRow[2], aSw[2];
    #pragma unroll
    for (int i = 0; i < 2; ++i) {
        int r = warp_m * 32 + i * 16 + (lane & 15);
        aRow[i] = (uint32_t)r * 128;
        aSw[i]  = (uint32_t)(r & 7);
    }
    // B frag addresses via ldsm_x4: jj in {0,1}, each yields 2 n8 frags
    uint32_t bRow[2], bSw[2];
    #pragma unroll
    for (int jj = 0; jj < 2; ++jj) {
        int r = warp_n * 32 + jj * 16 + (lane & 7) + ((lane >> 4) & 1) * 8;
        bRow[jj] = (uint32_t)r * 128;
        bSw[jj]  = (uint32_t)(r & 7);
    }
    const uint32_t ac0 = (uint32_t)(lane >> 4);        // 0/1 (k8 half for A)
    const uint32_t bc0 = (uint32_t)((lane >> 3) & 1);  // 0/1 (k8 half for B)

    int st = 0, ph = 0;
    for (int kt = 0; kt < NKT; ++kt) {
        MBARRIER_WAIT_PARITY(sFull + st * 8, ph);
        const uint32_t sb = sdyn + st * STAGE_B;
        const uint32_t ah = sb + 0 * PART_B;
        const uint32_t al = sb + 1 * PART_B;
        const uint32_t bh = sb + 2 * PART_B;
        const uint32_t bl = sb + 3 * PART_B;

        #pragma unroll
        for (int kk = 0; kk < 4; ++kk) {       // four k16 steps of BK=64
            uint32_t Ah[2][4], Al[2][4], Bh[2][4], Bl[2][4];
            const uint32_t ca = kk * 2 + ac0;
            const uint32_t cb = kk * 2 + bc0;
            #pragma unroll
            for (int i = 0; i < 2; ++i) {
                uint32_t off = aRow[i] + ((ca ^ aSw[i]) << 4);
                ldsm_x4(Ah[i], ah + off);
                ldsm_x4(Al[i], al + off);
            }
            #pragma unroll
            for (int jj = 0; jj < 2; ++jj) {
                uint32_t off = bRow[jj] + ((cb ^ bSw[jj]) << 4);
                ldsm_x4(Bh[jj], bh + off);
                ldsm_x4(Bl[jj], bl + off);
            }
            // term-major: 8 MMAs per term, reuse distance 8
            #pragma unroll
            for (int i = 0; i < 2; ++i)
                #pragma unroll
                for (int j = 0; j < 4; ++j)
                    mma16816(acc[i][j], Ah[i], &Bh[j >> 1][(j & 1) * 2]);
            #pragma unroll
            for (int i = 0; i < 2; ++i)
                #pragma unroll
                for (int j = 0; j < 4; ++j)
                    mma16816(acc[i][j], Ah[i], &Bl[j >> 1][(j & 1) * 2]);
            #pragma unroll
            for (int i = 0; i < 2; ++i)
                #pragma unroll
                for (int j = 0; j < 4; ++j)
                    mma16816(acc[i][j], Al[i], &Bh[j >> 1][(j & 1) * 2]);
        }
        if (lane == 0) MBARRIER_ARRIVE(sEmpty + st * 8);
        if (++st == STAGES) { st = 0; ph ^= 1; }
    }

    // epilogue: y = x * softplus(acc + b1) * s
    #pragma unroll
    for (int i = 0; i < 2; ++i) {
        const int r0 = rbase + warp_m * 32 + i * 16 + (lane >> 2);
        const int r1 = r0 + 8;
        const float s0 = g_s[r0], s1 = g_s[r1];
        #pragma unroll
        for (int j = 0; j < 4; ++j) {
            const int c = cbase + warp_n * 32 + j * 8 + (lane & 3) * 2;
            float2 bv = *reinterpret_cast<const float2*>(b1 + c);
            float2 x0 = *reinterpret_cast<const float2*>(x + (size_t)r0 * DDIM + c);
            float2 x1 = *reinterpret_cast<const float2*>(x + (size_t)r1 * DDIM + c);
            float2 o0, o1;
            o0.x = x0.x * softplusf(acc[i][j][0] + bv.x) * s0;
            o0.y = x0.y * softplusf(acc[i][j][1] + bv.y) * s0;
            o1.x = x1.x * softplusf(acc[i][j][2] + bv.x) * s1;
            o1.y = x1.y * softplusf(acc[i][j][3] + bv.y) * s1;
            *reinterpret_cast<float2*>(y + (size_t)r0 * DDIM + c) = o0;
            *reinterpret_cast<float2*>(y + (size_t)r1 * DDIM + c) = o1;
        }
    }
}

// ---------------------------------------------------------------------------
extern "C" void kernel_launch(void* const* d_in, const int* in_sizes, int n_in,
                              void* d_out, int out_size)
{
    const float* x  = (const float*)d_in[0];
    const float* W1 = (const float*)d_in[1];
    const float* b1 = (const float*)d_in[2];
    const float* W2 = (const float*)d_in[3];
    const float* b2 = (const float*)d_in[4];
    const float* W3 = (const float*)d_in[5];
    const float* b3 = (const float*)d_in[6];
    // d_in[7] = A is mathematically dead (multiplies zero-initialized h).
    float* y = (float*)d_out;

    cudaFuncSetAttribute(gemm_kernel,
                         cudaFuncAttributeMaxDynamicSharedMemorySize, GEMM_SMEM);

    prep_kernel<<<768, 256>>>(x, W1, W2, b2, W3, b3);

    dim3 grid(DDIM / 128, TOKENS / 128);   // (8, 32)
    gemm_kernel<<<grid, 544, GEMM_SMEM>>>(x, b1, y);
}